// round 1
// baseline (speedup 1.0000x reference)
#include <cuda_runtime.h>

// GRUModel: bidirectional GRU (B=32768, T=18, I=2, H=64) + fc1(128->24) + reshape + fc2(18->2)
// Strategy: one thread per batch element, h[64] in registers, weights in shared
// (broadcast loads, float4), directions sequential with W_hh reload.
// fc1/fc2 fused into the time loop via a per-thread 48-float accumulator.

#define BTOT   32768
#define TT     18
#define HH     64
#define NTHR   128

__device__ __forceinline__ float sig_(float x) {
    return 1.0f / (1.0f + __expf(-x));
}
__device__ __forceinline__ float tanh_(float x) {
    // tanh(x) = 2*sigmoid(2x) - 1 ; saturates correctly at +-inf
    return 2.0f / (1.0f + __expf(-2.0f * x)) - 1.0f;
}

extern __shared__ float smem[];

__global__ __launch_bounds__(NTHR)
void gru_fused_kernel(const float* __restrict__ x,
                      const float* __restrict__ w_ih_f, const float* __restrict__ w_hh_f,
                      const float* __restrict__ b_ih_f, const float* __restrict__ b_hh_f,
                      const float* __restrict__ w_ih_b, const float* __restrict__ w_hh_b,
                      const float* __restrict__ b_ih_b, const float* __restrict__ b_hh_b,
                      const float* __restrict__ fc1_w, const float* __restrict__ fc1_b,
                      const float* __restrict__ fc2_w, const float* __restrict__ fc2_b,
                      float* __restrict__ out)
{
    // ---- shared memory layout (floats) ----
    float* whh_sh  = smem;              // 12288  (192 x 64, current direction)
    float* wih_sh  = whh_sh + 12288;    // 384    (192 x 2)
    float* brz_sh  = wih_sh + 384;      // 128    (b_ih+b_hh for r,z gates)
    float* bnih_sh = brz_sh + 128;      // 64     (b_ih for n gate)
    float* bnhh_sh = bnih_sh + 64;      // 64     (b_hh for n gate)
    float* fc1w_sh = bnhh_sh + 64;      // 3072   (24 x 128)
    float* fc1b_sh = fc1w_sh + 3072;    // 32 (24 used)
    float* fc2w_sh = fc1b_sh + 32;      // 40 (36 used)
    float* fc2b_sh = fc2w_sh + 40;      // 8  (2 used)
    float* scratch = fc2b_sh + 8;       // 128*64 = 8192 (h_new staging, [i][tid])

    const int tid = threadIdx.x;
    const int b   = blockIdx.x * NTHR + tid;

    // ---- load fc1 / fc2 weights once ----
    for (int idx = tid; idx < 3072; idx += NTHR) fc1w_sh[idx] = fc1_w[idx];
    if (tid < 24) fc1b_sh[tid] = fc1_b[tid];
    if (tid < 36) fc2w_sh[tid] = fc2_w[tid];
    if (tid < 2)  fc2b_sh[tid] = fc2_b[tid];

    // per-thread fc2 accumulator (dynamically indexed -> local memory; tiny traffic)
    float acc2[48];
    #pragma unroll
    for (int i = 0; i < 48; i++) acc2[i] = 0.0f;

    float h[HH];
    const float* xb = x + (size_t)b * (TT * 2);

    for (int dir = 0; dir < 2; ++dir) {
        const float* whh = dir ? w_hh_b : w_hh_f;
        const float* wih = dir ? w_ih_b : w_ih_f;
        const float* bih = dir ? b_ih_b : b_ih_f;
        const float* bhh = dir ? b_hh_b : b_hh_f;

        __syncthreads();   // previous direction's shared use finished
        for (int idx = tid; idx < 12288; idx += NTHR) whh_sh[idx] = whh[idx];
        for (int idx = tid; idx < 384;   idx += NTHR) wih_sh[idx] = wih[idx];
        if (tid < 128) brz_sh[tid] = bih[tid] + bhh[tid];
        if (tid < 64) { bnih_sh[tid] = bih[128 + tid]; bnhh_sh[tid] = bhh[128 + tid]; }
        __syncthreads();

        #pragma unroll
        for (int j = 0; j < HH; j++) { h[j] = 0.0f; scratch[j * NTHR + tid] = 0.0f; }

        for (int s = 0; s < TT; ++s) {
            const int t = dir ? (TT - 1 - s) : s;   // x time index == output time index
            const float2 xv = *(const float2*)(xb + t * 2);
            const float x0 = xv.x, x1 = xv.y;

            // ---- h_new[i] = GRU gate update; old h in regs + scratch ----
            #pragma unroll 2
            for (int i = 0; i < HH; i++) {
                float aR = brz_sh[i]       + x0 * wih_sh[2*i]         + x1 * wih_sh[2*i + 1];
                float aZ = brz_sh[64 + i]  + x0 * wih_sh[2*(64 + i)]  + x1 * wih_sh[2*(64 + i) + 1];
                float aN = bnih_sh[i]      + x0 * wih_sh[2*(128 + i)] + x1 * wih_sh[2*(128 + i) + 1];

                float hR0 = 0.f, hZ0 = 0.f, hN0 = 0.f;
                float hR1 = 0.f, hZ1 = 0.f, hN1 = 0.f;
                const float4* wr = (const float4*)(whh_sh + i * 64);
                const float4* wz = (const float4*)(whh_sh + (64 + i) * 64);
                const float4* wn = (const float4*)(whh_sh + (128 + i) * 64);
                #pragma unroll
                for (int q = 0; q < 16; q += 2) {
                    float4 a0 = wr[q],   c0 = wz[q],   e0 = wn[q];
                    float4 a1 = wr[q+1], c1 = wz[q+1], e1 = wn[q+1];
                    const float h00 = h[4*q+0], h01 = h[4*q+1], h02 = h[4*q+2], h03 = h[4*q+3];
                    const float h10 = h[4*q+4], h11 = h[4*q+5], h12 = h[4*q+6], h13 = h[4*q+7];
                    hR0 += h00*a0.x + h01*a0.y + h02*a0.z + h03*a0.w;
                    hZ0 += h00*c0.x + h01*c0.y + h02*c0.z + h03*c0.w;
                    hN0 += h00*e0.x + h01*e0.y + h02*e0.z + h03*e0.w;
                    hR1 += h10*a1.x + h11*a1.y + h12*a1.z + h13*a1.w;
                    hZ1 += h10*c1.x + h11*c1.y + h12*c1.z + h13*c1.w;
                    hN1 += h10*e1.x + h11*e1.y + h12*e1.z + h13*e1.w;
                }
                const float r = sig_(aR + hR0 + hR1);
                const float z = sig_(aZ + hZ0 + hZ1);
                const float n = tanh_(aN + r * (hN0 + hN1 + bnhh_sh[i]));
                const float hold = scratch[i * NTHR + tid];
                scratch[i * NTHR + tid] = n + z * (hold - n);   // (1-z)*n + z*h
            }

            // ---- copy h_new -> registers (same thread wrote it; no sync needed) ----
            #pragma unroll
            for (int j = 0; j < HH; j++) h[j] = scratch[j * NTHR + tid];

            // ---- fused fc1 (this direction's half) + fc2 scatter ----
            const float* w1 = fc1w_sh + dir * 64;
            for (int k = 0; k < 24; k++) {
                float sacc = dir ? 0.0f : fc1b_sh[k];   // fc1 bias counted once
                const float4* wk = (const float4*)(w1 + k * 128);
                #pragma unroll
                for (int q = 0; q < 16; q++) {
                    float4 a = wk[q];
                    sacc += h[4*q+0]*a.x + h[4*q+1]*a.y + h[4*q+2]*a.z + h[4*q+3]*a.w;
                }
                const int n_  = t * 24 + k;        // flat index in (T,24)
                const int r_  = n_ / 18;           // row of (24,18) reshape
                const int j_  = n_ - r_ * 18;      // col
                acc2[2*r_ + 0] += sacc * fc2w_sh[j_];
                acc2[2*r_ + 1] += sacc * fc2w_sh[18 + j_];
            }
        }
    }

    float* ob = out + (size_t)b * 48;
    #pragma unroll
    for (int m = 0; m < 48; m++) ob[m] = acc2[m] + fc2b_sh[m & 1];
}

extern "C" void kernel_launch(void* const* d_in, const int* in_sizes, int n_in,
                              void* d_out, int out_size)
{
    const float* x      = (const float*)d_in[0];
    const float* w_ih_f = (const float*)d_in[1];
    const float* w_hh_f = (const float*)d_in[2];
    const float* b_ih_f = (const float*)d_in[3];
    const float* b_hh_f = (const float*)d_in[4];
    const float* w_ih_b = (const float*)d_in[5];
    const float* w_hh_b = (const float*)d_in[6];
    const float* b_ih_b = (const float*)d_in[7];
    const float* b_hh_b = (const float*)d_in[8];
    const float* fc1_w  = (const float*)d_in[9];
    const float* fc1_b  = (const float*)d_in[10];
    const float* fc2_w  = (const float*)d_in[11];
    const float* fc2_b  = (const float*)d_in[12];
    float* out = (float*)d_out;

    // shared: 12288+384+128+64+64+3072+32+40+8+8192 = 24272 floats
    const int smem_bytes = 24272 * (int)sizeof(float);
    cudaFuncSetAttribute(gru_fused_kernel,
                         cudaFuncAttributeMaxDynamicSharedMemorySize, smem_bytes);

    gru_fused_kernel<<<BTOT / NTHR, NTHR, smem_bytes>>>(
        x, w_ih_f, w_hh_f, b_ih_f, b_hh_f,
        w_ih_b, w_hh_b, b_ih_b, b_hh_b,
        fc1_w, fc1_b, fc2_w, fc2_b, out);
}